// round 12
// baseline (speedup 1.0000x reference)
#include <cuda_runtime.h>
#include <cuda_fp16.h>
#include <cstdint>

#define BATCH 16
#define CIN   512
#define COUT  512
#define HW    32
#define EPS   1e-8f
#define GAIN  0.014731391274719738f   // 1/sqrt(512*9)

#define PW    34
#define PPIX  1156
#define KC    64                      // halfs of K per step
#define TAPS  9
#define NCHUNK 8
#define NSTEPS 72                     // TAPS * NCHUNK

// ---------------- device scratch ----------------
__device__ float  g_wsq[CIN * COUT];                   // [i][o]
__device__ float  g_sigma[BATCH * COUT];               // [b][o], pre-scaled by GAIN
__device__ __half g_xsh[(size_t)BATCH * PPIX * CIN];   // [b][p'][i] modulated, zero-padded
__device__ __half g_w9h[9 * COUT * CIN];               // [tap][o][i]

// ---------------- PTX helpers ----------------
__device__ __forceinline__ uint32_t smem_u32(const void* p) {
    uint32_t a;
    asm("{ .reg .u64 t; cvta.to.shared.u64 t, %1; cvt.u32.u64 %0, t; }" : "=r"(a) : "l"(p));
    return a;
}
__device__ __forceinline__ void cpa16(uint32_t dst, const void* src) {
    asm volatile("cp.async.cg.shared.global [%0], [%1], 16;" :: "r"(dst), "l"(src));
}
#define CP_COMMIT()  asm volatile("cp.async.commit_group;" ::: "memory")
#define CP_WAIT(n)   asm volatile("cp.async.wait_group %0;" :: "n"(n) : "memory")

#define LDM_X4(r0, r1, r2, r3, a) \
    asm volatile("ldmatrix.sync.aligned.m8n8.x4.shared.b16 {%0,%1,%2,%3}, [%4];" \
        : "=r"(r0), "=r"(r1), "=r"(r2), "=r"(r3) : "r"(a))

#define MMA16816(c, a, b0, b1) \
    asm volatile("mma.sync.aligned.m16n8k16.row.col.f32.f16.f16.f32 " \
        "{%0,%1,%2,%3},{%4,%5,%6,%7},{%8,%9},{%0,%1,%2,%3};" \
        : "+f"((c)[0]), "+f"((c)[1]), "+f"((c)[2]), "+f"((c)[3]) \
        : "r"((a)[0]), "r"((a)[1]), "r"((a)[2]), "r"((a)[3]), "r"(b0), "r"(b1))

// ---------------- launch #1: fused modulated image + weight prep ----------
// grid (97, BATCH):
//   bx in [0,32): image row y=bx -> padded row yp=y+1
//   bx == 32   : zero padded rows yp=0, yp=33
//   bx in [33,97): wprep slice (batch-independent; linear id = (bx-33) + 64*b)
__global__ void prep_kernel(const float* __restrict__ x, const float* __restrict__ style,
                            const float* __restrict__ weight) {
    const int b   = blockIdx.y;
    const int bx  = blockIdx.x;
    const int tid = threadIdx.x;

    if (bx >= 33) {      // ---- wprep: wsq + w9h ----
        int idx = ((bx - 33) + 64 * b) * 256 + tid;   // 0 .. 262143
        const float* wp = weight + (size_t)idx * 9;
        int o = idx >> 9, i = idx & 511;
        float s = 0.f;
#pragma unroll
        for (int t = 0; t < 9; t++) {
            float w = wp[t];
            s += w * w;
            g_w9h[(size_t)t * (COUT * CIN) + o * CIN + i] = __float2half_rn(w);
        }
        g_wsq[i * COUT + o] = s;
        return;
    }

    if (bx == HW) {      // ---- zero padded rows yp=0 and yp=33 ----
        uint4 z = make_uint4(0, 0, 0, 0);
        uint4* p0 = (uint4*)&g_xsh[(size_t)b * PPIX * CIN];
        uint4* p1 = (uint4*)&g_xsh[((size_t)b * PPIX + 33 * PW) * CIN];
        for (int k = tid; k < PW * CIN / 8; k += 256) { p0[k] = z; p1[k] = z; }
        return;
    }

    // ---- modulated row ----
    __shared__ __half tile[CIN][34];
    __shared__ float  sst[CIN];

    const int y = bx;
    for (int k = tid; k < CIN; k += 256) sst[k] = style[b * CIN + k];
    __syncthreads();

    const float2* xrow = (const float2*)(x + (((size_t)b * CIN) * HW + y) * HW);
    for (int k = tid; k < CIN * 16; k += 256) {
        int ch = k >> 4, p2 = k & 15;
        float2 v = xrow[(size_t)ch * (HW * HW / 2) + p2];
        float s = sst[ch];
        *(__half2*)&tile[ch][p2 * 2] = __floats2half2_rn(v.x * s, v.y * s);
    }
    __syncthreads();

    __half* rowbase = &g_xsh[((size_t)b * PPIX + (size_t)(y + 1) * PW) * CIN];
    const int i2 = 2 * tid;
    for (int xp = 0; xp < PW; xp++) {
        __half2 h2;
        if (xp == 0 || xp == PW - 1) h2 = __floats2half2_rn(0.f, 0.f);
        else h2 = __halves2half2(tile[i2][xp - 1], tile[i2 + 1][xp - 1]);
        *(__half2*)&rowbase[(size_t)xp * CIN + i2] = h2;
    }
}

// ---------------- launches #2/#3: sigma (split to keep mma at launch #4) ----
__global__ void sigma_kernel(const float* __restrict__ style, int b0) {
    __shared__ float s2[CIN];
    int b = b0 + blockIdx.x, o = threadIdx.x;
    float sv = style[b * CIN + o];
    s2[o] = sv * sv;
    __syncthreads();
    float acc = 0.f;
#pragma unroll 8
    for (int i = 0; i < CIN; i++) acc = fmaf(s2[i], g_wsq[i * COUT + o], acc);
    g_sigma[b * COUT + o] = GAIN * rsqrtf(GAIN * GAIN * acc + EPS);
}

// ---------------- launch #4: main GEMM ----------------
// CTA 128 o x 128 real pixels, 8 warps, warp tile 64x32. 72 steps of KC=64.
// A: 3-stage ring; B: 204-row window per ic-chunk (2 buffers).
// Max window row read by ldsm = (96>>5)*34 + 15 + 35 + 35 + 16(np=1) = 203 -> BROWS=204.
#define SROWB 144
#define ATILE (128 * SROWB)        // 18432
#define BROWS 204
#define BTILE (BROWS * SROWB)      // 29376
#define SM_SIG (3 * ATILE + 2 * BTILE)       // 114048
#define SM_TOTAL (SM_SIG + 512)              // 114560

__global__ __launch_bounds__(256, 2)
void mma_kernel(float* __restrict__ out) {
    extern __shared__ __align__(16) char smem[];
    const uint32_t sAu = smem_u32(smem);
    const uint32_t sBu = sAu + 3 * ATILE;
    float* sSig = (float*)(smem + SM_SIG);

    const int tid  = threadIdx.x;
    const int wid  = tid >> 5, lane = tid & 31;
    const int m0   = (wid >> 2) * 64;
    const int n0   = (wid & 3) * 32;
    const int oBase = blockIdx.y * 128;
    const int b     = blockIdx.z;

    // sigma -> smem (pre-scaled by GAIN); visibility covered by step-0 barrier
    if (tid < 128) sSig[tid] = g_sigma[b * COUT + oBase + tid];

    const int rA = ((lane >> 3) & 1) * 8 + (lane & 7);
    const int kA = (lane >> 4) * 16;
    const int rB = (lane >> 4) * 8 + (lane & 7);
    const int kB = ((lane >> 3) & 1) * 16;
    const uint32_t aAddr0 = sAu + (uint32_t)(m0 + rA) * SROWB + kA;
    const uint32_t bAddr0 = sBu + (uint32_t)((n0 >> 5) * 34 + rB + 35) * SROWB + kB;

    const __half* bwin = g_xsh + ((size_t)b * PPIX + 136 * blockIdx.x) * CIN;

    float c[4][4][4];
#pragma unroll
    for (int mi = 0; mi < 4; mi++)
#pragma unroll
        for (int ni = 0; ni < 4; ni++)
#pragma unroll
            for (int j = 0; j < 4; j++) c[mi][ni][j] = 0.f;

    const int sr = tid >> 3;          // 0..31
    const int sc = tid & 7;           // 0..7
    const uint32_t dstA0 = sAu + (uint32_t)sr * SROWB + sc * 16;

    auto stageA = [&](int k2, int t2, int s2) {
        const __half* Asrc = g_w9h + (size_t)t2 * (COUT * CIN) + (size_t)oBase * CIN + k2 * KC;
        const uint32_t bo = (uint32_t)(s2 % 3) * ATILE;
#pragma unroll
        for (int h = 0; h < 4; h++) {
            const int r = sr + h * 32;
            cpa16(dstA0 + bo + (uint32_t)h * 32 * SROWB, Asrc + (size_t)r * CIN + sc * 8);
        }
    };
    auto stageBp = [&](int kN, int t) {
        const int r0 = t * 26;
        const int rend = (r0 + 26 <= BROWS) ? (r0 + 26) : BROWS;
        const int r = r0 + sr;
        if (r < rend) {
            const __half* src = bwin + (size_t)r * CIN + kN * KC + sc * 8;
            cpa16(sBu + (uint32_t)(kN & 1) * BTILE + (uint32_t)r * SROWB + sc * 16, src);
        }
    };

    auto compute = [&](int s, int k, uint32_t dltRow) {
        const uint32_t aB = aAddr0 + (uint32_t)(s % 3) * ATILE;
        const uint32_t bB = bAddr0 + (uint32_t)(k & 1) * BTILE + dltRow;
#pragma unroll
        for (int kt = 0; kt < 4; kt++) {
            uint32_t a[4][4], bb[4][2];
#pragma unroll
            for (int mi = 0; mi < 4; mi++)
                LDM_X4(a[mi][0], a[mi][1], a[mi][2], a[mi][3],
                       aB + (uint32_t)mi * 16 * SROWB + kt * 32);
#pragma unroll
            for (int np = 0; np < 2; np++)
                LDM_X4(bb[np * 2][0], bb[np * 2][1], bb[np * 2 + 1][0], bb[np * 2 + 1][1],
                       bB + (uint32_t)np * 16 * SROWB + kt * 32);
#pragma unroll
            for (int mi = 0; mi < 4; mi++)
#pragma unroll
                for (int ni = 0; ni < 4; ni++)
                    MMA16816(c[mi][ni], a[mi], bb[ni][0], bb[ni][1]);
        }
    };

    // prologue: g0 = {A(0), full B(0)}, g1 = {A(1)}
    stageA(0, 0, 0);
    for (int r = sr; r < BROWS; r += 32)
        cpa16(sBu + (uint32_t)r * SROWB + sc * 16, bwin + (size_t)r * CIN + sc * 8);
    CP_COMMIT();
    stageA(0, 1, 1);
    CP_COMMIT();

    int s = 0;
    for (int k = 0; k < NCHUNK; k++) {
#pragma unroll
        for (int t = 0; t < TAPS; t++, s++) {
            if (s == NSTEPS - 1) { CP_WAIT(0); } else { CP_WAIT(1); }
            __syncthreads();
            const int dlt = (t / 3 - 1) * PW + (t % 3 - 1);   // compile-time per t
            compute(s, k, (uint32_t)(dlt * SROWB));
            const int s2 = s + 2;
            if (s2 < NSTEPS) {
                const int k2 = s2 / TAPS;
                stageA(k2, s2 - k2 * TAPS, s2);
            }
            if (t < 8 && k + 1 < NCHUNK) stageBp(k + 1, t);
            CP_COMMIT();
        }
    }

    // ---- epilogue: sigma from smem, branch-free float2 stores ----
    const int g  = lane >> 2;
    const int t4 = lane & 3;
    const int gpBase = blockIdx.x * 128 + n0 + 2 * t4;
#pragma unroll
    for (int mi = 0; mi < 4; mi++) {
        const int oR = m0 + mi * 16 + g;
        const float sL = sSig[oR];
        const float sH = sSig[oR + 8];
        float* outL = out + ((size_t)b * COUT + oBase + oR) * (HW * HW);
        float* outH = outL + 8 * (HW * HW);
#pragma unroll
        for (int ni = 0; ni < 4; ni++) {
            const int gp = gpBase + ni * 8;
            *(float2*)&outL[gp] = make_float2(c[mi][ni][0] * sL, c[mi][ni][1] * sL);
            *(float2*)&outH[gp] = make_float2(c[mi][ni][2] * sH, c[mi][ni][3] * sH);
        }
    }
}

// ---------------- launch ----------------
extern "C" void kernel_launch(void* const* d_in, const int* in_sizes, int n_in,
                              void* d_out, int out_size) {
    const float* x      = (const float*)d_in[0];
    const float* style  = (const float*)d_in[1];
    const float* weight = (const float*)d_in[2];
    float* out = (float*)d_out;

    // 4 launches; ncu (-s 5 -c 1) lands on #4 = mma_kernel.
    prep_kernel<<<dim3(97, BATCH), 256>>>(x, style, weight);
    sigma_kernel<<<8, CIN>>>(style, 0);
    sigma_kernel<<<8, CIN>>>(style, 8);

    cudaFuncSetAttribute(mma_kernel, cudaFuncAttributeMaxDynamicSharedMemorySize, SM_TOTAL);
    mma_kernel<<<dim3(8, 4, BATCH), 256, SM_TOTAL>>>(out);
}

// round 13
// speedup vs baseline: 1.0509x; 1.0509x over previous
#include <cuda_runtime.h>
#include <cuda_fp16.h>
#include <cstdint>

#define BATCH 16
#define CIN   512
#define COUT  512
#define HW    32
#define EPS   1e-8f
#define GAIN  0.014731391274719738f   // 1/sqrt(512*9)

#define PW    34
#define PPIX  1156
#define KC    64                      // halfs of K per step
#define TAPS  9
#define NCHUNK 8
#define NSTEPS 72                     // TAPS * NCHUNK

// ---------------- device scratch ----------------
__device__ float  g_wsq[CIN * COUT];                   // [i][o]
__device__ float  g_sigma[BATCH * COUT];               // [b][o], pre-scaled by GAIN
__device__ __half g_xsh[(size_t)BATCH * PPIX * CIN];   // [b][p'][i] modulated, zero-padded
__device__ __half g_w9h[9 * COUT * CIN];               // [tap][o][i]

// ---------------- PTX helpers ----------------
__device__ __forceinline__ uint32_t smem_u32(const void* p) {
    uint32_t a;
    asm("{ .reg .u64 t; cvta.to.shared.u64 t, %1; cvt.u32.u64 %0, t; }" : "=r"(a) : "l"(p));
    return a;
}
__device__ __forceinline__ void cpa16(uint32_t dst, const void* src) {
    asm volatile("cp.async.cg.shared.global [%0], [%1], 16;" :: "r"(dst), "l"(src));
}
#define CP_COMMIT()  asm volatile("cp.async.commit_group;" ::: "memory")
#define CP_WAIT(n)   asm volatile("cp.async.wait_group %0;" :: "n"(n) : "memory")

#define LDM_X4(r0, r1, r2, r3, a) \
    asm volatile("ldmatrix.sync.aligned.m8n8.x4.shared.b16 {%0,%1,%2,%3}, [%4];" \
        : "=r"(r0), "=r"(r1), "=r"(r2), "=r"(r3) : "r"(a))

#define MMA16816(c, a, b0, b1) \
    asm volatile("mma.sync.aligned.m16n8k16.row.col.f32.f16.f16.f32 " \
        "{%0,%1,%2,%3},{%4,%5,%6,%7},{%8,%9},{%0,%1,%2,%3};" \
        : "+f"((c)[0]), "+f"((c)[1]), "+f"((c)[2]), "+f"((c)[3]) \
        : "r"((a)[0]), "r"((a)[1]), "r"((a)[2]), "r"((a)[3]), "r"(b0), "r"(b1))

// ---------------- launch #1: modulated padded image (R10 version) ----------
__global__ void xmod_kernel(const float* __restrict__ x, const float* __restrict__ style) {
    const int b   = blockIdx.y;
    const int bx  = blockIdx.x;
    const int tid = threadIdx.x;

    if (bx == HW) {     // zero padded rows yp=0 and yp=33
        uint4 z = make_uint4(0, 0, 0, 0);
        uint4* p0 = (uint4*)&g_xsh[(size_t)b * PPIX * CIN];
        uint4* p1 = (uint4*)&g_xsh[((size_t)b * PPIX + 33 * PW) * CIN];
        for (int k = tid; k < PW * CIN / 8; k += 256) { p0[k] = z; p1[k] = z; }
        return;
    }

    __shared__ __half tile[CIN][34];
    __shared__ float  sst[CIN];

    const int y = bx;
    for (int k = tid; k < CIN; k += 256) sst[k] = style[b * CIN + k];
    __syncthreads();

    const float2* xrow = (const float2*)(x + (((size_t)b * CIN) * HW + y) * HW);
    for (int k = tid; k < CIN * 16; k += 256) {
        int ch = k >> 4, p2 = k & 15;
        float2 v = xrow[(size_t)ch * (HW * HW / 2) + p2];
        float s = sst[ch];
        *(__half2*)&tile[ch][p2 * 2] = __floats2half2_rn(v.x * s, v.y * s);
    }
    __syncthreads();

    __half* rowbase = &g_xsh[((size_t)b * PPIX + (size_t)(y + 1) * PW) * CIN];
    const int i2 = 2 * tid;
    for (int xp = 0; xp < PW; xp++) {
        __half2 h2;
        if (xp == 0 || xp == PW - 1) h2 = __floats2half2_rn(0.f, 0.f);
        else h2 = __halves2half2(tile[i2][xp - 1], tile[i2 + 1][xp - 1]);
        *(__half2*)&rowbase[(size_t)xp * CIN + i2] = h2;
    }
}

// ---------------- launch #2: wsq + w9h ----------------
__global__ void wprep_kernel(const float* __restrict__ weight) {
    int idx = blockIdx.x * 256 + threadIdx.x;   // o*512 + i
    if (idx < COUT * CIN) {
        const float* wp = weight + (size_t)idx * 9;
        int o = idx >> 9, i = idx & 511;
        float s = 0.f;
#pragma unroll
        for (int t = 0; t < 9; t++) {
            float w = wp[t];
            s += w * w;
            g_w9h[(size_t)t * (COUT * CIN) + o * CIN + i] = __float2half_rn(w);
        }
        g_wsq[i * COUT + o] = s;
    }
}

// ---------------- launch #3: sigma (single launch, GAIN-prescaled) --------
__global__ void sigma_kernel(const float* __restrict__ style) {
    __shared__ float s2[CIN];
    int b = blockIdx.x, o = threadIdx.x;
    float sv = style[b * CIN + o];
    s2[o] = sv * sv;
    __syncthreads();
    float acc = 0.f;
#pragma unroll 8
    for (int i = 0; i < CIN; i++) acc = fmaf(s2[i], g_wsq[i * COUT + o], acc);
    g_sigma[b * COUT + o] = GAIN * rsqrtf(GAIN * GAIN * acc + EPS);
}

// ---------------- launch #4: main GEMM (R12 version) ----------------
// CTA 128 o x 128 real pixels, 8 warps, warp tile 64x32. 72 steps of KC=64.
// A: 3-stage ring; B: 204-row window per ic-chunk (2 buffers).
// Max window row read by ldsm = (96>>5)*34 + 15 + 35 + 35 + 16(np=1) = 203 -> BROWS=204.
#define SROWB 144
#define ATILE (128 * SROWB)        // 18432
#define BROWS 204
#define BTILE (BROWS * SROWB)      // 29376
#define SM_SIG (3 * ATILE + 2 * BTILE)       // 114048
#define SM_TOTAL (SM_SIG + 512)              // 114560

__global__ __launch_bounds__(256, 2)
void mma_kernel(float* __restrict__ out) {
    extern __shared__ __align__(16) char smem[];
    const uint32_t sAu = smem_u32(smem);
    const uint32_t sBu = sAu + 3 * ATILE;
    float* sSig = (float*)(smem + SM_SIG);

    const int tid  = threadIdx.x;
    const int wid  = tid >> 5, lane = tid & 31;
    const int m0   = (wid >> 2) * 64;
    const int n0   = (wid & 3) * 32;
    const int oBase = blockIdx.y * 128;
    const int b     = blockIdx.z;

    // sigma -> smem (pre-scaled by GAIN); visibility covered by step-0 barrier
    if (tid < 128) sSig[tid] = g_sigma[b * COUT + oBase + tid];

    const int rA = ((lane >> 3) & 1) * 8 + (lane & 7);
    const int kA = (lane >> 4) * 16;
    const int rB = (lane >> 4) * 8 + (lane & 7);
    const int kB = ((lane >> 3) & 1) * 16;
    const uint32_t aAddr0 = sAu + (uint32_t)(m0 + rA) * SROWB + kA;
    const uint32_t bAddr0 = sBu + (uint32_t)((n0 >> 5) * 34 + rB + 35) * SROWB + kB;

    const __half* bwin = g_xsh + ((size_t)b * PPIX + 136 * blockIdx.x) * CIN;

    float c[4][4][4];
#pragma unroll
    for (int mi = 0; mi < 4; mi++)
#pragma unroll
        for (int ni = 0; ni < 4; ni++)
#pragma unroll
            for (int j = 0; j < 4; j++) c[mi][ni][j] = 0.f;

    const int sr = tid >> 3;          // 0..31
    const int sc = tid & 7;           // 0..7
    const uint32_t dstA0 = sAu + (uint32_t)sr * SROWB + sc * 16;

    auto stageA = [&](int k2, int t2, int s2) {
        const __half* Asrc = g_w9h + (size_t)t2 * (COUT * CIN) + (size_t)oBase * CIN + k2 * KC;
        const uint32_t bo = (uint32_t)(s2 % 3) * ATILE;
#pragma unroll
        for (int h = 0; h < 4; h++) {
            const int r = sr + h * 32;
            cpa16(dstA0 + bo + (uint32_t)h * 32 * SROWB, Asrc + (size_t)r * CIN + sc * 8);
        }
    };
    auto stageBp = [&](int kN, int t) {
        const int r0 = t * 26;
        const int rend = (r0 + 26 <= BROWS) ? (r0 + 26) : BROWS;
        const int r = r0 + sr;
        if (r < rend) {
            const __half* src = bwin + (size_t)r * CIN + kN * KC + sc * 8;
            cpa16(sBu + (uint32_t)(kN & 1) * BTILE + (uint32_t)r * SROWB + sc * 16, src);
        }
    };

    auto compute = [&](int s, int k, uint32_t dltRow) {
        const uint32_t aB = aAddr0 + (uint32_t)(s % 3) * ATILE;
        const uint32_t bB = bAddr0 + (uint32_t)(k & 1) * BTILE + dltRow;
#pragma unroll
        for (int kt = 0; kt < 4; kt++) {
            uint32_t a[4][4], bb[4][2];
#pragma unroll
            for (int mi = 0; mi < 4; mi++)
                LDM_X4(a[mi][0], a[mi][1], a[mi][2], a[mi][3],
                       aB + (uint32_t)mi * 16 * SROWB + kt * 32);
#pragma unroll
            for (int np = 0; np < 2; np++)
                LDM_X4(bb[np * 2][0], bb[np * 2][1], bb[np * 2 + 1][0], bb[np * 2 + 1][1],
                       bB + (uint32_t)np * 16 * SROWB + kt * 32);
#pragma unroll
            for (int mi = 0; mi < 4; mi++)
#pragma unroll
                for (int ni = 0; ni < 4; ni++)
                    MMA16816(c[mi][ni], a[mi], bb[ni][0], bb[ni][1]);
        }
    };

    // prologue: g0 = {A(0), full B(0)}, g1 = {A(1)}
    stageA(0, 0, 0);
    for (int r = sr; r < BROWS; r += 32)
        cpa16(sBu + (uint32_t)r * SROWB + sc * 16, bwin + (size_t)r * CIN + sc * 8);
    CP_COMMIT();
    stageA(0, 1, 1);
    CP_COMMIT();

    int s = 0;
    for (int k = 0; k < NCHUNK; k++) {
#pragma unroll
        for (int t = 0; t < TAPS; t++, s++) {
            if (s == NSTEPS - 1) { CP_WAIT(0); } else { CP_WAIT(1); }
            __syncthreads();
            const int dlt = (t / 3 - 1) * PW + (t % 3 - 1);   // compile-time per t
            compute(s, k, (uint32_t)(dlt * SROWB));
            const int s2 = s + 2;
            if (s2 < NSTEPS) {
                const int k2 = s2 / TAPS;
                stageA(k2, s2 - k2 * TAPS, s2);
            }
            if (t < 8 && k + 1 < NCHUNK) stageBp(k + 1, t);
            CP_COMMIT();
        }
    }

    // ---- epilogue: sigma from smem, branch-free float2 stores ----
    const int g  = lane >> 2;
    const int t4 = lane & 3;
    const int gpBase = blockIdx.x * 128 + n0 + 2 * t4;
#pragma unroll
    for (int mi = 0; mi < 4; mi++) {
        const int oR = m0 + mi * 16 + g;
        const float sL = sSig[oR];
        const float sH = sSig[oR + 8];
        float* outL = out + ((size_t)b * COUT + oBase + oR) * (HW * HW);
        float* outH = outL + 8 * (HW * HW);
#pragma unroll
        for (int ni = 0; ni < 4; ni++) {
            const int gp = gpBase + ni * 8;
            *(float2*)&outL[gp] = make_float2(c[mi][ni][0] * sL, c[mi][ni][1] * sL);
            *(float2*)&outH[gp] = make_float2(c[mi][ni][2] * sH, c[mi][ni][3] * sH);
        }
    }
}

// ---------------- launch ----------------
extern "C" void kernel_launch(void* const* d_in, const int* in_sizes, int n_in,
                              void* d_out, int out_size) {
    const float* x      = (const float*)d_in[0];
    const float* style  = (const float*)d_in[1];
    const float* weight = (const float*)d_in[2];
    float* out = (float*)d_out;

    // 4 launches; ncu (-s 5 -c 1) lands on #4 = mma_kernel.
    xmod_kernel<<<dim3(HW + 1, BATCH), 256>>>(x, style);
    wprep_kernel<<<(COUT * CIN + 255) / 256, 256>>>(weight);
    sigma_kernel<<<BATCH, CIN>>>(style);

    cudaFuncSetAttribute(mma_kernel, cudaFuncAttributeMaxDynamicSharedMemorySize, SM_TOTAL);
    mma_kernel<<<dim3(8, 4, BATCH), 256, SM_TOTAL>>>(out);
}

// round 14
// speedup vs baseline: 1.0870x; 1.0344x over previous
#include <cuda_runtime.h>
#include <cuda_fp16.h>
#include <cstdint>

#define BATCH 16
#define CIN   512
#define COUT  512
#define HW    32
#define EPS   1e-8f
#define GAIN  0.014731391274719738f   // 1/sqrt(512*9)

#define PW    34
#define PPIX  1156
#define KC    64                      // halfs of K per step
#define TAPS  9
#define NCHUNK 8
#define NSTEPS 72                     // TAPS * NCHUNK

// ---------------- device scratch ----------------
__device__ float  g_wsq[CIN * COUT];                   // [i][o]
__device__ float  g_sigma[BATCH * COUT];               // [b][o], pre-scaled by GAIN
__device__ __half g_xsh[(size_t)BATCH * PPIX * CIN];   // [b][p'][i] modulated, zero-padded
__device__ __half g_w9h[9 * COUT * CIN];               // [tap][o][i]

// ---------------- PTX helpers ----------------
__device__ __forceinline__ uint32_t smem_u32(const void* p) {
    uint32_t a;
    asm("{ .reg .u64 t; cvta.to.shared.u64 t, %1; cvt.u32.u64 %0, t; }" : "=r"(a) : "l"(p));
    return a;
}
__device__ __forceinline__ void cpa16(uint32_t dst, const void* src) {
    asm volatile("cp.async.cg.shared.global [%0], [%1], 16;" :: "r"(dst), "l"(src));
}
#define CP_COMMIT()  asm volatile("cp.async.commit_group;" ::: "memory")
#define CP_WAIT(n)   asm volatile("cp.async.wait_group %0;" :: "n"(n) : "memory")

#define LDM_X4(r0, r1, r2, r3, a) \
    asm volatile("ldmatrix.sync.aligned.m8n8.x4.shared.b16 {%0,%1,%2,%3}, [%4];" \
        : "=r"(r0), "=r"(r1), "=r"(r2), "=r"(r3) : "r"(a))

#define MMA16816(c, a, b0, b1) \
    asm volatile("mma.sync.aligned.m16n8k16.row.col.f32.f16.f16.f32 " \
        "{%0,%1,%2,%3},{%4,%5,%6,%7},{%8,%9},{%0,%1,%2,%3};" \
        : "+f"((c)[0]), "+f"((c)[1]), "+f"((c)[2]), "+f"((c)[3]) \
        : "r"((a)[0]), "r"((a)[1]), "r"((a)[2]), "r"((a)[3]), "r"(b0), "r"(b1))

// ---------------- launch #1: modulated padded image (v2) ----------------
// grid (33, 2, BATCH), 256 threads.
//   bx in [0,32): image row y=bx, channel half ci=blockIdx.y (256 ch)
//   bx == 32   : zero padded row (ci=0 -> yp 0, ci=1 -> yp 33)
__global__ void xmod_kernel(const float* __restrict__ x, const float* __restrict__ style) {
    const int b   = blockIdx.z;
    const int bx  = blockIdx.x;
    const int ci  = blockIdx.y;
    const int tid = threadIdx.x;

    if (bx == HW) {     // zero one padded border row (full 512 channels)
        const int yp = ci ? 33 : 0;
        uint4 z = make_uint4(0, 0, 0, 0);
        uint4* p = (uint4*)&g_xsh[((size_t)b * PPIX + (size_t)yp * PW) * CIN];
        for (int k = tid; k < PW * CIN / 8; k += 256) p[k] = z;
        return;
    }

    __shared__ __half tl[32][258];   // [px][ch], pitch 516 B (conflict-light)
    __shared__ float  sst[256];

    const int y = bx;
    const int cBase = ci * 256;
    sst[tid] = style[b * CIN + cBase + tid];
    __syncthreads();

    // pass 1: coalesced float2 reads of x row, modulate, scatter into [px][ch]
    const float2* xrow = (const float2*)(x + (((size_t)b * CIN + cBase) * HW + y) * HW);
    for (int k = tid; k < 256 * 16; k += 256) {
        int ch = k >> 4, p2 = k & 15;
        float2 v = xrow[(size_t)ch * (HW * HW / 2) + p2];
        float s = sst[ch];
        tl[2 * p2][ch]     = __float2half_rn(v.x * s);
        tl[2 * p2 + 1][ch] = __float2half_rn(v.y * s);
    }
    __syncthreads();

    // pass 2: contiguous half2 smem reads, coalesced 512B gmem writes per xp
    __half* rowbase = &g_xsh[((size_t)b * PPIX + (size_t)(y + 1) * PW) * CIN + cBase];
    for (int idx = tid; idx < 34 * 128; idx += 256) {
        int xp = idx >> 7, pr = idx & 127;
        __half2 h2;
        if (xp == 0 || xp == PW - 1) h2 = __floats2half2_rn(0.f, 0.f);
        else h2 = *(__half2*)&tl[xp - 1][2 * pr];
        *(__half2*)&rowbase[(size_t)xp * CIN + 2 * pr] = h2;
    }
}

// ---------------- launch #2: wsq + w9h ----------------
__global__ void wprep_kernel(const float* __restrict__ weight) {
    int idx = blockIdx.x * 256 + threadIdx.x;   // o*512 + i
    if (idx < COUT * CIN) {
        const float* wp = weight + (size_t)idx * 9;
        int o = idx >> 9, i = idx & 511;
        float s = 0.f;
#pragma unroll
        for (int t = 0; t < 9; t++) {
            float w = wp[t];
            s += w * w;
            g_w9h[(size_t)t * (COUT * CIN) + o * CIN + i] = __float2half_rn(w);
        }
        g_wsq[i * COUT + o] = s;
    }
}

// ---------------- launch #3: sigma (GAIN-prescaled) ----------------
__global__ void sigma_kernel(const float* __restrict__ style) {
    __shared__ float s2[CIN];
    int b = blockIdx.x, o = threadIdx.x;
    float sv = style[b * CIN + o];
    s2[o] = sv * sv;
    __syncthreads();
    float acc = 0.f;
#pragma unroll 8
    for (int i = 0; i < CIN; i++) acc = fmaf(s2[i], g_wsq[i * COUT + o], acc);
    g_sigma[b * COUT + o] = GAIN * rsqrtf(GAIN * GAIN * acc + EPS);
}

// ---------------- launch #4: main GEMM (unchanged from R13) ----------------
#define SROWB 144
#define ATILE (128 * SROWB)        // 18432
#define BROWS 204
#define BTILE (BROWS * SROWB)      // 29376
#define SM_SIG (3 * ATILE + 2 * BTILE)       // 114048
#define SM_TOTAL (SM_SIG + 512)              // 114560

__global__ __launch_bounds__(256, 2)
void mma_kernel(float* __restrict__ out) {
    extern __shared__ __align__(16) char smem[];
    const uint32_t sAu = smem_u32(smem);
    const uint32_t sBu = sAu + 3 * ATILE;
    float* sSig = (float*)(smem + SM_SIG);

    const int tid  = threadIdx.x;
    const int wid  = tid >> 5, lane = tid & 31;
    const int m0   = (wid >> 2) * 64;
    const int n0   = (wid & 3) * 32;
    const int oBase = blockIdx.y * 128;
    const int b     = blockIdx.z;

    if (tid < 128) sSig[tid] = g_sigma[b * COUT + oBase + tid];

    const int rA = ((lane >> 3) & 1) * 8 + (lane & 7);
    const int kA = (lane >> 4) * 16;
    const int rB = (lane >> 4) * 8 + (lane & 7);
    const int kB = ((lane >> 3) & 1) * 16;
    const uint32_t aAddr0 = sAu + (uint32_t)(m0 + rA) * SROWB + kA;
    const uint32_t bAddr0 = sBu + (uint32_t)((n0 >> 5) * 34 + rB + 35) * SROWB + kB;

    const __half* bwin = g_xsh + ((size_t)b * PPIX + 136 * blockIdx.x) * CIN;

    float c[4][4][4];
#pragma unroll
    for (int mi = 0; mi < 4; mi++)
#pragma unroll
        for (int ni = 0; ni < 4; ni++)
#pragma unroll
            for (int j = 0; j < 4; j++) c[mi][ni][j] = 0.f;

    const int sr = tid >> 3;          // 0..31
    const int sc = tid & 7;           // 0..7
    const uint32_t dstA0 = sAu + (uint32_t)sr * SROWB + sc * 16;

    auto stageA = [&](int k2, int t2, int s2) {
        const __half* Asrc = g_w9h + (size_t)t2 * (COUT * CIN) + (size_t)oBase * CIN + k2 * KC;
        const uint32_t bo = (uint32_t)(s2 % 3) * ATILE;
#pragma unroll
        for (int h = 0; h < 4; h++) {
            const int r = sr + h * 32;
            cpa16(dstA0 + bo + (uint32_t)h * 32 * SROWB, Asrc + (size_t)r * CIN + sc * 8);
        }
    };
    auto stageBp = [&](int kN, int t) {
        const int r0 = t * 26;
        const int rend = (r0 + 26 <= BROWS) ? (r0 + 26) : BROWS;
        const int r = r0 + sr;
        if (r < rend) {
            const __half* src = bwin + (size_t)r * CIN + kN * KC + sc * 8;
            cpa16(sBu + (uint32_t)(kN & 1) * BTILE + (uint32_t)r * SROWB + sc * 16, src);
        }
    };

    auto compute = [&](int s, int k, uint32_t dltRow) {
        const uint32_t aB = aAddr0 + (uint32_t)(s % 3) * ATILE;
        const uint32_t bB = bAddr0 + (uint32_t)(k & 1) * BTILE + dltRow;
#pragma unroll
        for (int kt = 0; kt < 4; kt++) {
            uint32_t a[4][4], bb[4][2];
#pragma unroll
            for (int mi = 0; mi < 4; mi++)
                LDM_X4(a[mi][0], a[mi][1], a[mi][2], a[mi][3],
                       aB + (uint32_t)mi * 16 * SROWB + kt * 32);
#pragma unroll
            for (int np = 0; np < 2; np++)
                LDM_X4(bb[np * 2][0], bb[np * 2][1], bb[np * 2 + 1][0], bb[np * 2 + 1][1],
                       bB + (uint32_t)np * 16 * SROWB + kt * 32);
#pragma unroll
            for (int mi = 0; mi < 4; mi++)
#pragma unroll
                for (int ni = 0; ni < 4; ni++)
                    MMA16816(c[mi][ni], a[mi], bb[ni][0], bb[ni][1]);
        }
    };

    // prologue: g0 = {A(0), full B(0)}, g1 = {A(1)}
    stageA(0, 0, 0);
    for (int r = sr; r < BROWS; r += 32)
        cpa16(sBu + (uint32_t)r * SROWB + sc * 16, bwin + (size_t)r * CIN + sc * 8);
    CP_COMMIT();
    stageA(0, 1, 1);
    CP_COMMIT();

    int s = 0;
    for (int k = 0; k < NCHUNK; k++) {
#pragma unroll
        for (int t = 0; t < TAPS; t++, s++) {
            if (s == NSTEPS - 1) { CP_WAIT(0); } else { CP_WAIT(1); }
            __syncthreads();
            const int dlt = (t / 3 - 1) * PW + (t % 3 - 1);   // compile-time per t
            compute(s, k, (uint32_t)(dlt * SROWB));
            const int s2 = s + 2;
            if (s2 < NSTEPS) {
                const int k2 = s2 / TAPS;
                stageA(k2, s2 - k2 * TAPS, s2);
            }
            if (t < 8 && k + 1 < NCHUNK) stageBp(k + 1, t);
            CP_COMMIT();
        }
    }

    // ---- epilogue ----
    const int g  = lane >> 2;
    const int t4 = lane & 3;
    const int gpBase = blockIdx.x * 128 + n0 + 2 * t4;
#pragma unroll
    for (int mi = 0; mi < 4; mi++) {
        const int oR = m0 + mi * 16 + g;
        const float sL = sSig[oR];
        const float sH = sSig[oR + 8];
        float* outL = out + ((size_t)b * COUT + oBase + oR) * (HW * HW);
        float* outH = outL + 8 * (HW * HW);
#pragma unroll
        for (int ni = 0; ni < 4; ni++) {
            const int gp = gpBase + ni * 8;
            *(float2*)&outL[gp] = make_float2(c[mi][ni][0] * sL, c[mi][ni][1] * sL);
            *(float2*)&outH[gp] = make_float2(c[mi][ni][2] * sH, c[mi][ni][3] * sH);
        }
    }
}

// ---------------- launch ----------------
extern "C" void kernel_launch(void* const* d_in, const int* in_sizes, int n_in,
                              void* d_out, int out_size) {
    const float* x      = (const float*)d_in[0];
    const float* style  = (const float*)d_in[1];
    const float* weight = (const float*)d_in[2];
    float* out = (float*)d_out;

    // 4 launches; ncu lands on #4 = mma_kernel.
    xmod_kernel<<<dim3(33, 2, BATCH), 256>>>(x, style);
    wprep_kernel<<<(COUT * CIN + 255) / 256, 256>>>(weight);
    sigma_kernel<<<BATCH, CIN>>>(style);

    cudaFuncSetAttribute(mma_kernel, cudaFuncAttributeMaxDynamicSharedMemorySize, SM_TOTAL);
    mma_kernel<<<dim3(8, 4, BATCH), 256, SM_TOTAL>>>(out);
}

// round 15
// speedup vs baseline: 1.1007x; 1.0126x over previous
#include <cuda_runtime.h>
#include <cuda_fp16.h>
#include <cstdint>

#define BATCH 16
#define CIN   512
#define COUT  512
#define HW    32
#define EPS   1e-8f
#define GAIN  0.014731391274719738f   // 1/sqrt(512*9)

#define PW    34
#define PPIX  1156
#define KC    64                      // halfs of K per step
#define TAPS  9
#define NCHUNK 8
#define NSTEPS 72                     // TAPS * NCHUNK

// ---------------- device scratch ----------------
__device__ float  g_wsq[CIN * COUT];                   // [i][o]
__device__ float  g_sigma[BATCH * COUT];               // [b][o], pre-scaled by GAIN
__device__ __half g_xsh[(size_t)BATCH * PPIX * CIN];   // [b][p'][i] modulated, zero-padded
__device__ __half g_w9h[9 * COUT * CIN];               // [tap][o][i]

// ---------------- PTX helpers ----------------
__device__ __forceinline__ uint32_t smem_u32(const void* p) {
    uint32_t a;
    asm("{ .reg .u64 t; cvta.to.shared.u64 t, %1; cvt.u32.u64 %0, t; }" : "=r"(a) : "l"(p));
    return a;
}
__device__ __forceinline__ void cpa16(uint32_t dst, const void* src) {
    asm volatile("cp.async.cg.shared.global [%0], [%1], 16;" :: "r"(dst), "l"(src));
}
#define CP_COMMIT()  asm volatile("cp.async.commit_group;" ::: "memory")
#define CP_WAIT(n)   asm volatile("cp.async.wait_group %0;" :: "n"(n) : "memory")

#define LDM_X4(r0, r1, r2, r3, a) \
    asm volatile("ldmatrix.sync.aligned.m8n8.x4.shared.b16 {%0,%1,%2,%3}, [%4];" \
        : "=r"(r0), "=r"(r1), "=r"(r2), "=r"(r3) : "r"(a))

#define MMA16816(c, a, b0, b1) \
    asm volatile("mma.sync.aligned.m16n8k16.row.col.f32.f16.f16.f32 " \
        "{%0,%1,%2,%3},{%4,%5,%6,%7},{%8,%9},{%0,%1,%2,%3};" \
        : "+f"((c)[0]), "+f"((c)[1]), "+f"((c)[2]), "+f"((c)[3]) \
        : "r"((a)[0]), "r"((a)[1]), "r"((a)[2]), "r"((a)[3]), "r"(b0), "r"(b1))

// ---------------- launch #1: fused prep (xmod + wprep, dynamic smem) ------
// 1D grid, 2080 blocks of 256:
//   idx in [0, 1056): xmod  — b = idx/66, ci = (idx%66)/33, bx = (idx%66)%33
//       bx in [0,32): image row y=bx, channel half ci; bx==32: zero border row
//   idx in [1056, 2080): wprep slice (idx-1056)
#define XMOD_SMEM (32 * 258 * 2 + 256 * 4)   // 17536 B
__global__ void prep_kernel(const float* __restrict__ x, const float* __restrict__ style,
                            const float* __restrict__ weight) {
    const int gidx = blockIdx.x;
    const int tid  = threadIdx.x;

    if (gidx >= 1056) {   // ---- wprep: wsq + w9h ----
        int idx = (gidx - 1056) * 256 + tid;   // 0 .. 262143 = o*512 + i
        const float* wp = weight + (size_t)idx * 9;
        int o = idx >> 9, i = idx & 511;
        float s = 0.f;
#pragma unroll
        for (int t = 0; t < 9; t++) {
            float w = wp[t];
            s += w * w;
            g_w9h[(size_t)t * (COUT * CIN) + o * CIN + i] = __float2half_rn(w);
        }
        g_wsq[i * COUT + o] = s;
        return;
    }

    // ---- xmod ----
    const int b   = gidx / 66;
    const int rem = gidx - b * 66;
    const int ci  = rem / 33;
    const int bx  = rem - ci * 33;

    if (bx == HW) {     // zero one padded border row (full 512 channels)
        const int yp = ci ? 33 : 0;
        uint4 z = make_uint4(0, 0, 0, 0);
        uint4* p = (uint4*)&g_xsh[((size_t)b * PPIX + (size_t)yp * PW) * CIN];
        for (int k = tid; k < PW * CIN / 8; k += 256) p[k] = z;
        return;
    }

    extern __shared__ __align__(16) char dsm[];
    __half (*tl)[258] = (__half(*)[258])dsm;            // [32][258]
    float* sst = (float*)(dsm + 32 * 258 * 2);          // [256]

    const int y = bx;
    const int cBase = ci * 256;
    sst[tid] = style[b * CIN + cBase + tid];
    __syncthreads();

    const float2* xrow = (const float2*)(x + (((size_t)b * CIN + cBase) * HW + y) * HW);
    for (int k = tid; k < 256 * 16; k += 256) {
        int ch = k >> 4, p2 = k & 15;
        float2 v = xrow[(size_t)ch * (HW * HW / 2) + p2];
        float s = sst[ch];
        tl[2 * p2][ch]     = __float2half_rn(v.x * s);
        tl[2 * p2 + 1][ch] = __float2half_rn(v.y * s);
    }
    __syncthreads();

    __half* rowbase = &g_xsh[((size_t)b * PPIX + (size_t)(y + 1) * PW) * CIN + cBase];
    for (int idx = tid; idx < 34 * 128; idx += 256) {
        int xp = idx >> 7, pr = idx & 127;
        __half2 h2;
        if (xp == 0 || xp == PW - 1) h2 = __floats2half2_rn(0.f, 0.f);
        else h2 = *(__half2*)&tl[xp - 1][2 * pr];
        *(__half2*)&rowbase[(size_t)xp * CIN + 2 * pr] = h2;
    }
}

// ---------------- launch #2: sigma (GAIN-prescaled) ----------------
__global__ void sigma_kernel(const float* __restrict__ style) {
    __shared__ float s2[CIN];
    int b = blockIdx.x, o = threadIdx.x;
    float sv = style[b * CIN + o];
    s2[o] = sv * sv;
    __syncthreads();
    float acc = 0.f;
#pragma unroll 8
    for (int i = 0; i < CIN; i++) acc = fmaf(s2[i], g_wsq[i * COUT + o], acc);
    g_sigma[b * COUT + o] = GAIN * rsqrtf(GAIN * GAIN * acc + EPS);
}

// ---------------- launch #3: main GEMM (unchanged from R14) ----------------
#define SROWB 144
#define ATILE (128 * SROWB)        // 18432
#define BROWS 204
#define BTILE (BROWS * SROWB)      // 29376
#define SM_SIG (3 * ATILE + 2 * BTILE)       // 114048
#define SM_TOTAL (SM_SIG + 512)              // 114560

__global__ __launch_bounds__(256, 2)
void mma_kernel(float* __restrict__ out) {
    extern __shared__ __align__(16) char smem[];
    const uint32_t sAu = smem_u32(smem);
    const uint32_t sBu = sAu + 3 * ATILE;
    float* sSig = (float*)(smem + SM_SIG);

    const int tid  = threadIdx.x;
    const int wid  = tid >> 5, lane = tid & 31;
    const int m0   = (wid >> 2) * 64;
    const int n0   = (wid & 3) * 32;
    const int oBase = blockIdx.y * 128;
    const int b     = blockIdx.z;

    if (tid < 128) sSig[tid] = g_sigma[b * COUT + oBase + tid];

    const int rA = ((lane >> 3) & 1) * 8 + (lane & 7);
    const int kA = (lane >> 4) * 16;
    const int rB = (lane >> 4) * 8 + (lane & 7);
    const int kB = ((lane >> 3) & 1) * 16;
    const uint32_t aAddr0 = sAu + (uint32_t)(m0 + rA) * SROWB + kA;
    const uint32_t bAddr0 = sBu + (uint32_t)((n0 >> 5) * 34 + rB + 35) * SROWB + kB;

    const __half* bwin = g_xsh + ((size_t)b * PPIX + 136 * blockIdx.x) * CIN;

    float c[4][4][4];
#pragma unroll
    for (int mi = 0; mi < 4; mi++)
#pragma unroll
        for (int ni = 0; ni < 4; ni++)
#pragma unroll
            for (int j = 0; j < 4; j++) c[mi][ni][j] = 0.f;

    const int sr = tid >> 3;          // 0..31
    const int sc = tid & 7;           // 0..7
    const uint32_t dstA0 = sAu + (uint32_t)sr * SROWB + sc * 16;

    auto stageA = [&](int k2, int t2, int s2) {
        const __half* Asrc = g_w9h + (size_t)t2 * (COUT * CIN) + (size_t)oBase * CIN + k2 * KC;
        const uint32_t bo = (uint32_t)(s2 % 3) * ATILE;
#pragma unroll
        for (int h = 0; h < 4; h++) {
            const int r = sr + h * 32;
            cpa16(dstA0 + bo + (uint32_t)h * 32 * SROWB, Asrc + (size_t)r * CIN + sc * 8);
        }
    };
    auto stageBp = [&](int kN, int t) {
        const int r0 = t * 26;
        const int rend = (r0 + 26 <= BROWS) ? (r0 + 26) : BROWS;
        const int r = r0 + sr;
        if (r < rend) {
            const __half* src = bwin + (size_t)r * CIN + kN * KC + sc * 8;
            cpa16(sBu + (uint32_t)(kN & 1) * BTILE + (uint32_t)r * SROWB + sc * 16, src);
        }
    };

    auto compute = [&](int s, int k, uint32_t dltRow) {
        const uint32_t aB = aAddr0 + (uint32_t)(s % 3) * ATILE;
        const uint32_t bB = bAddr0 + (uint32_t)(k & 1) * BTILE + dltRow;
#pragma unroll
        for (int kt = 0; kt < 4; kt++) {
            uint32_t a[4][4], bb[4][2];
#pragma unroll
            for (int mi = 0; mi < 4; mi++)
                LDM_X4(a[mi][0], a[mi][1], a[mi][2], a[mi][3],
                       aB + (uint32_t)mi * 16 * SROWB + kt * 32);
#pragma unroll
            for (int np = 0; np < 2; np++)
                LDM_X4(bb[np * 2][0], bb[np * 2][1], bb[np * 2 + 1][0], bb[np * 2 + 1][1],
                       bB + (uint32_t)np * 16 * SROWB + kt * 32);
#pragma unroll
            for (int mi = 0; mi < 4; mi++)
#pragma unroll
                for (int ni = 0; ni < 4; ni++)
                    MMA16816(c[mi][ni], a[mi], bb[ni][0], bb[ni][1]);
        }
    };

    // prologue: g0 = {A(0), full B(0)}, g1 = {A(1)}
    stageA(0, 0, 0);
    for (int r = sr; r < BROWS; r += 32)
        cpa16(sBu + (uint32_t)r * SROWB + sc * 16, bwin + (size_t)r * CIN + sc * 8);
    CP_COMMIT();
    stageA(0, 1, 1);
    CP_COMMIT();

    int s = 0;
    for (int k = 0; k < NCHUNK; k++) {
#pragma unroll
        for (int t = 0; t < TAPS; t++, s++) {
            if (s == NSTEPS - 1) { CP_WAIT(0); } else { CP_WAIT(1); }
            __syncthreads();
            const int dlt = (t / 3 - 1) * PW + (t % 3 - 1);   // compile-time per t
            compute(s, k, (uint32_t)(dlt * SROWB));
            const int s2 = s + 2;
            if (s2 < NSTEPS) {
                const int k2 = s2 / TAPS;
                stageA(k2, s2 - k2 * TAPS, s2);
            }
            if (t < 8 && k + 1 < NCHUNK) stageBp(k + 1, t);
            CP_COMMIT();
        }
    }

    // ---- epilogue ----
    const int g  = lane >> 2;
    const int t4 = lane & 3;
    const int gpBase = blockIdx.x * 128 + n0 + 2 * t4;
#pragma unroll
    for (int mi = 0; mi < 4; mi++) {
        const int oR = m0 + mi * 16 + g;
        const float sL = sSig[oR];
        const float sH = sSig[oR + 8];
        float* outL = out + ((size_t)b * COUT + oBase + oR) * (HW * HW);
        float* outH = outL + 8 * (HW * HW);
#pragma unroll
        for (int ni = 0; ni < 4; ni++) {
            const int gp = gpBase + ni * 8;
            *(float2*)&outL[gp] = make_float2(c[mi][ni][0] * sL, c[mi][ni][1] * sL);
            *(float2*)&outH[gp] = make_float2(c[mi][ni][2] * sH, c[mi][ni][3] * sH);
        }
    }
}

// ---------------- launch ----------------
extern "C" void kernel_launch(void* const* d_in, const int* in_sizes, int n_in,
                              void* d_out, int out_size) {
    const float* x      = (const float*)d_in[0];
    const float* style  = (const float*)d_in[1];
    const float* weight = (const float*)d_in[2];
    float* out = (float*)d_out;

    prep_kernel<<<2080, 256, XMOD_SMEM>>>(x, style, weight);
    sigma_kernel<<<BATCH, CIN>>>(style);

    cudaFuncSetAttribute(mma_kernel, cudaFuncAttributeMaxDynamicSharedMemorySize, SM_TOTAL);
    mma_kernel<<<dim3(8, 4, BATCH), 256, SM_TOTAL>>>(out);
}